// round 5
// baseline (speedup 1.0000x reference)
#include <cuda_runtime.h>
#include <math.h>

// Problem constants
// B=8, N=4096, C=512, NH=8, HD=64, R=8, H=W=64, M=64, EPS=1e-3, scale=1/8

#define NB   8
#define NSEQ 4096
#define CD   512
#define NHH  8
#define HDD  64

// ---------------- scratch (device globals; no allocation allowed) ----------------
__device__ float g_q[(size_t)NB * NSEQ * CD];      // [B, N, nh*64+hd]  64MB
__device__ float g_attn[(size_t)NB * NSEQ * CD];   // [B, N, nh*64+hd]  64MB
__device__ float g_fpart[(size_t)8 * 512 * 512];   // conv partials per ry split, 8MB
__device__ float g_ln[512 * 512];                  // layernormed fmap [B*64, C]
__device__ float g_kv[512 * 1024];                 // [B*64, 2C]
__device__ float g_wqp[512 * 512];                 // permuted Wq

// ---------------- Wq column permutation ----------------
// dst col d = nh*64+hd  <-  src col hd*8+nh
__global__ void permute_wq_kernel(const float* __restrict__ Wq) {
    int i = blockIdx.x * 256 + threadIdx.x;       // 262144 total
    int k = i >> 9;
    int d = i & 511;
    int nh = d >> 6;
    int hd = d & 63;
    g_wqp[i] = Wq[(k << 9) + (hd << 3) + nh];
}

// ---------------- 128x64 tiled fp32 GEMM, 8x4 microtile ----------------
// C[row, col] = sum_k A[row,k] * B[k,col] (+ bias[col])
// grid.x = M/128, grid.y = N/64, 256 threads.
__global__ void gemm128_kernel(const float* __restrict__ A, const float* __restrict__ B,
                               float* __restrict__ C, const float* __restrict__ bias,
                               int K, int Ncols) {
    __shared__ float As[16][128];
    __shared__ float Bs[16][64];
    const int tid = threadIdx.x;
    const int tx = tid & 15, ty = tid >> 4;          // compute: 4 cols, 8 rows
    const int row0 = blockIdx.x << 7;
    const int col0 = blockIdx.y << 6;
    const int lr = tid >> 1, lk = (tid & 1) << 3;    // A loader: row 0..127, k 0/8
    const int bk = tid >> 4, bc = (tid & 15) << 2;   // B loader: k-row, col-group

    float acc[8][4];
#pragma unroll
    for (int i = 0; i < 8; i++)
#pragma unroll
        for (int j = 0; j < 4; j++) acc[i][j] = 0.f;

    const float* Aptr = A + (size_t)(row0 + lr) * K + lk;
    const float* Bptr = B + (size_t)bk * Ncols + col0 + bc;

    for (int k0 = 0; k0 < K; k0 += 16) {
        float4 a0 = *(const float4*)(Aptr + k0);
        float4 a1 = *(const float4*)(Aptr + k0 + 4);
        As[lk + 0][lr] = a0.x; As[lk + 1][lr] = a0.y;
        As[lk + 2][lr] = a0.z; As[lk + 3][lr] = a0.w;
        As[lk + 4][lr] = a1.x; As[lk + 5][lr] = a1.y;
        As[lk + 6][lr] = a1.z; As[lk + 7][lr] = a1.w;
        *(float4*)&Bs[bk][bc] = *(const float4*)(Bptr + (size_t)k0 * Ncols);
        __syncthreads();
#pragma unroll
        for (int kk = 0; kk < 16; kk++) {
            float4 b  = *(const float4*)&Bs[kk][tx << 2];
            float4 aA = *(const float4*)&As[kk][ty << 3];
            float4 aB = *(const float4*)&As[kk][(ty << 3) + 4];
            float av[8] = {aA.x, aA.y, aA.z, aA.w, aB.x, aB.y, aB.z, aB.w};
#pragma unroll
            for (int i = 0; i < 8; i++) {
                acc[i][0] += av[i] * b.x; acc[i][1] += av[i] * b.y;
                acc[i][2] += av[i] * b.z; acc[i][3] += av[i] * b.w;
            }
        }
        __syncthreads();
    }

    float4 bb = make_float4(0.f, 0.f, 0.f, 0.f);
    if (bias) bb = *(const float4*)&bias[col0 + (tx << 2)];
#pragma unroll
    for (int i = 0; i < 8; i++) {
        int row = row0 + (ty << 3) + i;
        float4 o = make_float4(acc[i][0] + bb.x, acc[i][1] + bb.y,
                               acc[i][2] + bb.z, acc[i][3] + bb.w);
        *(float4*)&C[(size_t)row * Ncols + col0 + (tx << 2)] = o;
    }
}

// ---------------- conv as patch-GEMM (stride 8, kernel 8, pad 0) ----------------
// rows = b*64 + (my*8+mx), cols = co, K split by ry (blockIdx.z).
// For fixed ry the K-slice of a patch is 4096 CONTIGUOUS floats in x.
// 128x64 tiles: grid = (4, 8, 8).
__global__ void conv_gemm_kernel(const float* __restrict__ x, const float* __restrict__ W) {
    __shared__ float As[16][128];
    __shared__ float Bs[16][64];
    const int tid = threadIdx.x;
    const int tx = tid & 15, ty = tid >> 4;
    const int row0 = blockIdx.x << 7;
    const int col0 = blockIdx.y << 6;
    const int ry = blockIdx.z;
    const int lr = tid >> 1, lk = (tid & 1) << 3;
    const int bk = tid >> 4, bc = (tid & 15) << 2;

    const int row = row0 + lr;
    const int b = row >> 6, m = row & 63;
    const int my = m >> 3, mx = m & 7;
    // x[b, (my*8+ry)*64 + mx*8 + rx, ci]; offset within slice = rx*512+ci = klocal
    const float* xbase = x + ((size_t)(b << 12) + ((my << 3) + ry) * 64 + (mx << 3)) * 512 + lk;
    // W[ry][rx][ci][co] flat row = ry*4096 + klocal
    const float* Wbase = W + ((size_t)ry * 4096 + bk) * 512 + col0 + bc;

    float acc[8][4];
#pragma unroll
    for (int i = 0; i < 8; i++)
#pragma unroll
        for (int j = 0; j < 4; j++) acc[i][j] = 0.f;

    for (int k0 = 0; k0 < 4096; k0 += 16) {
        float4 a0 = *(const float4*)(xbase + k0);
        float4 a1 = *(const float4*)(xbase + k0 + 4);
        As[lk + 0][lr] = a0.x; As[lk + 1][lr] = a0.y;
        As[lk + 2][lr] = a0.z; As[lk + 3][lr] = a0.w;
        As[lk + 4][lr] = a1.x; As[lk + 5][lr] = a1.y;
        As[lk + 6][lr] = a1.z; As[lk + 7][lr] = a1.w;
        *(float4*)&Bs[bk][bc] = *(const float4*)(Wbase + (size_t)k0 * 512);
        __syncthreads();
#pragma unroll
        for (int kk = 0; kk < 16; kk++) {
            float4 b2 = *(const float4*)&Bs[kk][tx << 2];
            float4 aA = *(const float4*)&As[kk][ty << 3];
            float4 aB = *(const float4*)&As[kk][(ty << 3) + 4];
            float av[8] = {aA.x, aA.y, aA.z, aA.w, aB.x, aB.y, aB.z, aB.w};
#pragma unroll
            for (int i = 0; i < 8; i++) {
                acc[i][0] += av[i] * b2.x; acc[i][1] += av[i] * b2.y;
                acc[i][2] += av[i] * b2.z; acc[i][3] += av[i] * b2.w;
            }
        }
        __syncthreads();
    }

#pragma unroll
    for (int i = 0; i < 8; i++) {
        int r = row0 + (ty << 3) + i;
        float4 o = make_float4(acc[i][0], acc[i][1], acc[i][2], acc[i][3]);
        *(float4*)&g_fpart[((size_t)ry * 512 + r) * 512 + col0 + (tx << 2)] = o;
    }
}

// ---------------- sum conv partials + layernorm ----------------
__device__ __forceinline__ float warpSum(float v) {
#pragma unroll
    for (int o = 16; o; o >>= 1) v += __shfl_xor_sync(0xffffffffu, v, o);
    return v;
}

__global__ void ln_kernel(const float* __restrict__ gamma, const float* __restrict__ beta) {
    const int row = blockIdx.x;       // 512 rows
    const int tid = threadIdx.x;      // 128 threads, 4 cols each
    float4 v = make_float4(0.f, 0.f, 0.f, 0.f);
#pragma unroll
    for (int z = 0; z < 8; z++) {
        float4 p = *(const float4*)&g_fpart[((size_t)z * 512 + row) * 512 + (tid << 2)];
        v.x += p.x; v.y += p.y; v.z += p.z; v.w += p.w;
    }
    float s = v.x + v.y + v.z + v.w;
    float s2 = v.x * v.x + v.y * v.y + v.z * v.z + v.w * v.w;
    s = warpSum(s);
    s2 = warpSum(s2);
    __shared__ float sh[8];
    int w = tid >> 5, l = tid & 31;
    if (l == 0) { sh[w] = s; sh[4 + w] = s2; }
    __syncthreads();
    float S  = sh[0] + sh[1] + sh[2] + sh[3];
    float S2 = sh[4] + sh[5] + sh[6] + sh[7];
    float mean = S * (1.f / 512.f);
    float var = S2 * (1.f / 512.f) - mean * mean;
    float rstd = rsqrtf(var + 1e-3f);
    float4 g = *(const float4*)&gamma[tid << 2];
    float4 be = *(const float4*)&beta[tid << 2];
    float4 o;
    o.x = (v.x - mean) * rstd * g.x + be.x;
    o.y = (v.y - mean) * rstd * g.y + be.y;
    o.z = (v.z - mean) * rstd * g.z + be.z;
    o.w = (v.w - mean) * rstd * g.w + be.w;
    *(float4*)&g_ln[(size_t)row * 512 + (tid << 2)] = o;
}

// ---------------- attention: per (b, nh), M=64 K/V resident in shared ----------------
// grid = (32, NH, B), 128 threads, thread = one query row.
// smem: ks[64*64] | vs[64*64] | ps[128*65]
#define ATT_SMEM ((4096 + 4096 + 128 * 65) * 4)

__global__ void attention_kernel(const float* __restrict__ q,
                                 const float* __restrict__ kv,
                                 float* __restrict__ out) {
    extern __shared__ float sm[];
    float* ks = sm;
    float* vs = sm + 4096;
    float* ps = sm + 8192;

    const int b  = blockIdx.z;
    const int nh = blockIdx.y;
    const int n0 = blockIdx.x << 7;
    const int tid = threadIdx.x;

    // load K,V tiles: kv row = b*64+m, K at col nh*64+hd, V at col 512+nh*64+hd
    for (int i = tid; i < 1024; i += 128) {      // float4 index over 64x16
        int m = i >> 4, h4 = i & 15;
        const float* base = kv + (size_t)((b << 6) + m) * 1024 + (nh << 6);
        ((float4*)ks)[i] = ((const float4*)base)[h4];
        ((float4*)vs)[i] = ((const float4*)(base + 512))[h4];
    }
    __syncthreads();

    const int row = n0 + tid;
    const float* qsrc = q + ((size_t)(b << 12) + row) * 512 + (nh << 6);
    float4 qr[16];
#pragma unroll
    for (int i = 0; i < 16; i++) qr[i] = ((const float4*)qsrc)[i];

    // pass 1: scores -> shared (stride 65, conflict-free)
    float maxv = -1e30f;
    for (int m = 0; m < 64; m++) {
        const float4* kr = (const float4*)(ks + (m << 6));
        float acc = 0.f;
#pragma unroll
        for (int i = 0; i < 16; i++) {
            float4 kk = kr[i];
            acc += qr[i].x * kk.x + qr[i].y * kk.y + qr[i].z * kk.z + qr[i].w * kk.w;
        }
        acc *= 0.125f;
        ps[tid * 65 + m] = acc;
        maxv = fmaxf(maxv, acc);
    }
    float ssum = 0.f;
    for (int m = 0; m < 64; m++) {
        float e = __expf(ps[tid * 65 + m] - maxv);
        ps[tid * 65 + m] = e;
        ssum += e;
    }
    const float inv = 1.f / ssum;

    float4 o[16];
#pragma unroll
    for (int i = 0; i < 16; i++) o[i] = make_float4(0.f, 0.f, 0.f, 0.f);
    for (int m = 0; m < 64; m++) {
        float p = ps[tid * 65 + m] * inv;
        const float4* vr = (const float4*)(vs + (m << 6));
#pragma unroll
        for (int i = 0; i < 16; i++) {
            float4 vv = vr[i];
            o[i].x += p * vv.x; o[i].y += p * vv.y; o[i].z += p * vv.z; o[i].w += p * vv.w;
        }
    }

    float4* dst = (float4*)(out + ((size_t)(b << 12) + row) * 512 + (nh << 6));
#pragma unroll
    for (int i = 0; i < 16; i++) dst[i] = o[i];
}

// ---------------- launch ----------------
extern "C" void kernel_launch(void* const* d_in, const int* in_sizes, int n_in,
                              void* d_out, int out_size) {
    const float* x     = (const float*)d_in[0];
    const float* Wq    = (const float*)d_in[1];
    const float* Wkv   = (const float*)d_in[2];
    const float* convw = (const float*)d_in[3];
    const float* gamma = (const float*)d_in[4];
    const float* beta  = (const float*)d_in[5];
    const float* Wp    = (const float*)d_in[6];
    const float* bp    = (const float*)d_in[7];
    float* out = (float*)d_out;

    float *p_q, *p_attn, *p_ln, *p_kv, *p_wqp;
    cudaGetSymbolAddress((void**)&p_q,    g_q);
    cudaGetSymbolAddress((void**)&p_attn, g_attn);
    cudaGetSymbolAddress((void**)&p_ln,   g_ln);
    cudaGetSymbolAddress((void**)&p_kv,   g_kv);
    cudaGetSymbolAddress((void**)&p_wqp,  g_wqp);

    cudaFuncSetAttribute(attention_kernel,
                         cudaFuncAttributeMaxDynamicSharedMemorySize, ATT_SMEM);

    // 1. permute Wq columns so q comes out in [B,N, nh*64+hd]
    permute_wq_kernel<<<1024, 256>>>(Wq);
    // 2. conv as patch-GEMM, K split 8-way by ry into partial buffers
    conv_gemm_kernel<<<dim3(4, 8, 8), 256>>>(x, convw);
    // 3. sum partials + layernorm
    ln_kernel<<<512, 128>>>(gamma, beta);
    // 4. kv = ln @ Wkv   [512 x 1024]
    gemm128_kernel<<<dim3(4, 16), 256>>>(p_ln, Wkv, p_kv, nullptr, 512, 1024);
    // 5. q = x @ Wq_perm [32768 x 512]
    gemm128_kernel<<<dim3(256, 8), 256>>>(x, p_wqp, p_q, nullptr, 512, 512);
    // 6. attention per (b, nh)
    attention_kernel<<<dim3(32, NHH, NB), 128, ATT_SMEM>>>(p_q, p_kv, p_attn);
    // 7. final projection + bias -> d_out
    gemm128_kernel<<<dim3(256, 8), 256>>>(p_attn, Wp, out, bp, 512, 512);
}